// round 2
// baseline (speedup 1.0000x reference)
#include <cuda_runtime.h>

#define NCHUNK 105
#define CPAD   112
#define HID    512
#define IND1   128
#define NROWS  220000
#define KD     512
#define KT     32
#define NKT    (KD / KT)   // 16 k-tiles
#define TILE_R 64

// ---------------- device scratch (no allocations allowed) ----------------
__device__ float g_x  [NCHUNK * IND1];
__device__ float g_h1 [NCHUNK * HID];
__device__ float g_h2 [NCHUNK * HID];
__device__ float g_rep[NCHUNK * HID];

// ---------------- packed f32x2 FMA (Blackwell sm_103a) -------------------
__device__ __forceinline__ void ffma2(unsigned long long& d,
                                      unsigned long long a,
                                      unsigned long long b) {
    asm("fma.rn.f32x2 %0, %1, %2, %0;" : "+l"(d) : "l"(a), "l"(b));
}

// ---------------- build x = [pref_embedding | chunk_emb] -----------------
__global__ __launch_bounds__(256)
void build_x_kernel(const float* __restrict__ preference,
                    const float* __restrict__ pref_emb,
                    const float* __restrict__ chunk_emb) {
    __shared__ float pe[64];
    int tid = threadIdx.x;
    if (tid < 64) {
        pe[tid] = preference[0] * pref_emb[tid] + preference[1] * pref_emb[64 + tid];
    }
    __syncthreads();
    for (int i = tid; i < NCHUNK * IND1; i += blockDim.x) {
        int c = i >> 7;
        int k = i & 127;
        g_x[i] = (k < 64) ? pe[k] : chunk_emb[c * 64 + (k - 64)];
    }
}

// ---------------- generic MLP layer: out[c][j] = act(b[j] + in[c]·W[j]) --
// grid: (HID/(16*JITER), ceil(NCHUNK/8)), block 512.
// Warp computes JITER outputs j for 8 chunks; k split across lanes, shfl-reduce.
template <int IND, bool RELU>
__global__ __launch_bounds__(512)
void layer_kernel(const float* __restrict__ in,
                  const float* __restrict__ W,
                  const float* __restrict__ bias,
                  float* __restrict__ out) {
    constexpr int JITER = 2;
    constexpr int Q = IND / 4;           // float4 per row
    __shared__ float4 in_s[8][Q];

    int tid  = threadIdx.x;
    int lane = tid & 31;
    int warp = tid >> 5;
    int cbase = blockIdx.y * 8;

    for (int i = tid; i < 8 * Q; i += 512) {
        int c = i / Q;
        int q = i % Q;
        float4 v = make_float4(0.f, 0.f, 0.f, 0.f);
        if (cbase + c < NCHUNK)
            v = reinterpret_cast<const float4*>(in)[(cbase + c) * Q + q];
        in_s[c][q] = v;
    }
    __syncthreads();

    for (int t = 0; t < JITER; t++) {
        int j = blockIdx.x * (16 * JITER) + warp * JITER + t;
        float acc[8];
#pragma unroll
        for (int c = 0; c < 8; c++) acc[c] = 0.f;

        const float4* Wr = reinterpret_cast<const float4*>(W) + (size_t)j * Q;
        for (int i = lane; i < Q; i += 32) {
            float4 w = Wr[i];
#pragma unroll
            for (int c = 0; c < 8; c++) {
                float4 x = in_s[c][i];
                acc[c] += w.x * x.x + w.y * x.y + w.z * x.z + w.w * x.w;
            }
        }
#pragma unroll
        for (int c = 0; c < 8; c++) {
            float v = acc[c];
#pragma unroll
            for (int off = 16; off; off >>= 1)
                v += __shfl_down_sync(0xffffffffu, v, off);
            if (lane == 0 && (cbase + c) < NCHUNK) {
                v += bias[j];
                if (RELU) v = fmaxf(v, 0.f);
                out[(cbase + c) * HID + j] = v;
            }
        }
    }
}

// ---------------- big GEMM: out[c][r] = rep[c] . ws[r] -------------------
// Block: 64 rows x 112 chunks (7 padded). 512 threads.
// Thread: 2 rows x 7 chunks, f32x2 accumulators paired over adjacent k.
__global__ __launch_bounds__(512, 2)
void big_kernel(const float* __restrict__ ws, float* __restrict__ out) {
    __shared__ float rep_s[CPAD * KT];   // [c][k]  (128B rows -> broadcast reads)
    __shared__ float ws_s [TILE_R * KT]; // [r][k]  swizzled 128B rows

    int tid  = threadIdx.x;
    int lane = tid & 31;
    int warp = tid >> 5;
    long long blk = blockIdx.x;

    unsigned long long acc[2][7];
#pragma unroll
    for (int i = 0; i < 2; i++)
#pragma unroll
        for (int j = 0; j < 7; j++) acc[i][j] = 0ull;

    // staging assignments
    int wr = tid >> 3;            // ws row within tile (0..63)
    int wq = tid & 7;             // float4 index within k-tile (0..7)
    long long grow = blk * TILE_R + wr;
    if (grow >= NROWS) grow = 0;  // clamp (values never stored)
    const float4* wsrow = reinterpret_cast<const float4*>(ws) + grow * (KD / 4);

    const float4* rep4 = reinterpret_cast<const float4*>(g_rep);

    for (int kt = 0; kt < NKT; kt++) {
        // register-stage next tile (LDG overlaps previous compute)
        float4 wv = wsrow[kt * 8 + wq];

        float4 rv0 = make_float4(0.f, 0.f, 0.f, 0.f);
        float4 rv1 = make_float4(0.f, 0.f, 0.f, 0.f);
        {
            int c = tid >> 3, q = tid & 7;
            if (c < NCHUNK) rv0 = rep4[c * (KD / 4) + kt * 8 + q];
        }
        int i2 = tid + 512;
        if (i2 < CPAD * 8) {
            int c = i2 >> 3, q = i2 & 7;
            if (c < NCHUNK) rv1 = rep4[c * (KD / 4) + kt * 8 + q];
        }

        __syncthreads();   // previous compute done, safe to overwrite

        // store ws with SW128 swizzle (conflict-free column reads later)
        {
            unsigned off = (unsigned)(wr * 128 + wq * 16);
            off ^= (off >> 3) & 0x70;
            *reinterpret_cast<float4*>(reinterpret_cast<char*>(ws_s) + off) = wv;
        }
        {
            int c = tid >> 3, q = tid & 7;
            *reinterpret_cast<float4*>(rep_s + c * KT + q * 4) = rv0;
        }
        if (i2 < CPAD * 8) {
            int c = i2 >> 3, q = i2 & 7;
            *reinterpret_cast<float4*>(rep_s + c * KT + q * 4) = rv1;
        }

        __syncthreads();

#pragma unroll
        for (int kq = 0; kq < 8; kq++) {
            unsigned off0 = (unsigned)(lane * 128 + kq * 16);
            off0 ^= (off0 >> 3) & 0x70;
            unsigned off1 = (unsigned)((lane + 32) * 128 + kq * 16);
            off1 ^= (off1 >> 3) & 0x70;
            ulonglong2 a0 = *reinterpret_cast<const ulonglong2*>(
                reinterpret_cast<const char*>(ws_s) + off0);
            ulonglong2 a1 = *reinterpret_cast<const ulonglong2*>(
                reinterpret_cast<const char*>(ws_s) + off1);
#pragma unroll
            for (int j = 0; j < 7; j++) {
                int c = warp + 16 * j;
                ulonglong2 bq = *reinterpret_cast<const ulonglong2*>(
                    rep_s + c * KT + kq * 4);
                ffma2(acc[0][j], a0.x, bq.x);
                ffma2(acc[0][j], a0.y, bq.y);
                ffma2(acc[1][j], a1.x, bq.x);
                ffma2(acc[1][j], a1.y, bq.y);
            }
        }
    }

    // epilogue: combine even/odd-k partial lanes, store
    long long rg0 = blk * TILE_R + lane;
    long long rg1 = rg0 + 32;
#pragma unroll
    for (int j = 0; j < 7; j++) {
        int c = warp + 16 * j;
        if (c >= NCHUNK) continue;
        float2 p0 = *reinterpret_cast<float2*>(&acc[0][j]);
        float2 p1 = *reinterpret_cast<float2*>(&acc[1][j]);
        float v0 = p0.x + p0.y;
        float v1 = p1.x + p1.y;
        if (rg0 < NROWS) out[(size_t)c * NROWS + rg0] = v0;
        if (rg1 < NROWS) out[(size_t)c * NROWS + rg1] = v1;
    }
}

// ---------------------------- launcher -----------------------------------
extern "C" void kernel_launch(void* const* d_in, const int* in_sizes, int n_in,
                              void* d_out, int out_size) {
    const float* preference = (const float*)d_in[0];
    const float* pref_emb   = (const float*)d_in[1];
    const float* chunk_emb  = (const float*)d_in[2];
    const float* W1         = (const float*)d_in[3];
    const float* b1         = (const float*)d_in[4];
    const float* W2         = (const float*)d_in[5];
    const float* b2         = (const float*)d_in[6];
    const float* W3         = (const float*)d_in[7];
    const float* b3         = (const float*)d_in[8];
    const float* ws         = (const float*)d_in[9];
    float* out = (float*)d_out;

    float *px, *ph1, *ph2, *prep;
    cudaGetSymbolAddress((void**)&px,   g_x);
    cudaGetSymbolAddress((void**)&ph1,  g_h1);
    cudaGetSymbolAddress((void**)&ph2,  g_h2);
    cudaGetSymbolAddress((void**)&prep, g_rep);

    build_x_kernel<<<1, 256>>>(preference, pref_emb, chunk_emb);

    dim3 lgrid(HID / 32, (NCHUNK + 7) / 8);  // 16 x 14
    layer_kernel<IND1, true ><<<lgrid, 512>>>(px,  W1, b1, ph1);
    layer_kernel<HID,  true ><<<lgrid, 512>>>(ph1, W2, b2, ph2);
    layer_kernel<HID,  false><<<lgrid, 512>>>(ph2, W3, b3, prep);

    int nblocks = (NROWS + TILE_R - 1) / TILE_R;  // 3438
    big_kernel<<<nblocks, 512>>>(ws, out);
}

// round 4
// speedup vs baseline: 4.0237x; 4.0237x over previous
#include <cuda_runtime.h>
#include <cuda_fp16.h>
#include <cstdint>

#define NCHUNK 105
#define HID    512
#define IND1   128
#define NROWS  220000
#define KD     512

// ---- big GEMM tiling ----
#define MT    128          // M tile (ws rows)
#define NTP   128          // padded N (chunks, 105 -> 128)
#define KC    64           // K chunk staged per iteration
#define NKC   8            // 512/64
#define ASTRIDE_H 72       // halves per A_s row (64 + 8 pad) -> conflict-free ldmatrix
#define BSTRIDE_H 520      // halves per B_s row (512 + 8 pad)
#define B_BYTES  (NTP * BSTRIDE_H * 2)     // 133120
#define A_BYTES  (MT * ASTRIDE_H * 2)      // 18432
#define SMEM_TOTAL (B_BYTES + 2 * A_BYTES) // 169984

// ---------------- device scratch ----------------
__device__ float  g_x  [NCHUNK * IND1];
__device__ float  g_h1 [NCHUNK * HID];
__device__ float  g_h2 [NCHUNK * HID];
__device__ __half g_Bh [NTP * HID];        // fp16 image of rep (rows 105..127 zero)

// ---------------- PTX helpers ----------------
__device__ __forceinline__ uint32_t smem_u32_of(const void* p) {
    uint32_t a;
    asm("{ .reg .u64 t; cvta.to.shared.u64 t, %1; cvt.u32.u64 %0, t; }" : "=r"(a) : "l"(p));
    return a;
}
__device__ __forceinline__ void ldsm4(uint32_t* r, uint32_t addr) {
    asm volatile("ldmatrix.sync.aligned.m8n8.x4.shared.b16 {%0,%1,%2,%3}, [%4];"
                 : "=r"(r[0]), "=r"(r[1]), "=r"(r[2]), "=r"(r[3]) : "r"(addr));
}
__device__ __forceinline__ void mma16816(float* d, const uint32_t* a, const uint32_t* b) {
    asm volatile(
        "mma.sync.aligned.m16n8k16.row.col.f32.f16.f16.f32 "
        "{%0,%1,%2,%3}, {%4,%5,%6,%7}, {%8,%9}, {%0,%1,%2,%3};"
        : "+f"(d[0]), "+f"(d[1]), "+f"(d[2]), "+f"(d[3])
        : "r"(a[0]), "r"(a[1]), "r"(a[2]), "r"(a[3]), "r"(b[0]), "r"(b[1]));
}

// ---------------- build x = [pref_embedding | chunk_emb] -----------------
__global__ __launch_bounds__(256)
void build_x_kernel(const float* __restrict__ preference,
                    const float* __restrict__ pref_emb,
                    const float* __restrict__ chunk_emb) {
    __shared__ float pe[64];
    int tid = threadIdx.x;
    if (tid < 64)
        pe[tid] = preference[0] * pref_emb[tid] + preference[1] * pref_emb[64 + tid];
    __syncthreads();
    for (int i = tid; i < NCHUNK * IND1; i += blockDim.x) {
        int c = i >> 7, k = i & 127;
        g_x[i] = (k < 64) ? pe[k] : chunk_emb[c * 64 + (k - 64)];
    }
    // zero pad rows of the B image (never touched by layer3)
    for (int i = tid; i < (NTP - NCHUNK) * HID; i += blockDim.x)
        g_Bh[NCHUNK * HID + i] = __float2half(0.f);
}

// ---------------- MLP layer (proven passing structure) -------------------
template <int IND, bool RELU, bool EMITB>
__global__ __launch_bounds__(512)
void layer_kernel(const float* __restrict__ in, const float* __restrict__ W,
                  const float* __restrict__ bias, float* __restrict__ out) {
    constexpr int JITER = 2;
    constexpr int Q = IND / 4;
    __shared__ float4 in_s[8][Q];

    int tid = threadIdx.x, lane = tid & 31, warp = tid >> 5;
    int cbase = blockIdx.y * 8;

    for (int i = tid; i < 8 * Q; i += 512) {
        int c = i / Q, q = i % Q;
        float4 v = make_float4(0.f, 0.f, 0.f, 0.f);
        if (cbase + c < NCHUNK)
            v = reinterpret_cast<const float4*>(in)[(cbase + c) * Q + q];
        in_s[c][q] = v;
    }
    __syncthreads();

    for (int t = 0; t < JITER; t++) {
        int j = blockIdx.x * (16 * JITER) + warp * JITER + t;
        float acc[8];
#pragma unroll
        for (int c = 0; c < 8; c++) acc[c] = 0.f;
        const float4* Wr = reinterpret_cast<const float4*>(W) + (size_t)j * Q;
        for (int i = lane; i < Q; i += 32) {
            float4 w = Wr[i];
#pragma unroll
            for (int c = 0; c < 8; c++) {
                float4 x = in_s[c][i];
                acc[c] += w.x * x.x + w.y * x.y + w.z * x.z + w.w * x.w;
            }
        }
#pragma unroll
        for (int c = 0; c < 8; c++) {
            float v = acc[c];
#pragma unroll
            for (int off = 16; off; off >>= 1) v += __shfl_down_sync(0xffffffffu, v, off);
            if (lane == 0 && (cbase + c) < NCHUNK) {
                v += bias[j];
                if (RELU) v = fmaxf(v, 0.f);
                if (EMITB)
                    g_Bh[(cbase + c) * HID + j] = __float2half_rn(v);
                else
                    out[(cbase + c) * HID + j] = v;
            }
        }
    }
}

// ---------------- big GEMM: out[n][m] = ws[m] . rep[n] (HMMA fp16) -------
__global__ __launch_bounds__(512, 1)
void big_kernel(const float* __restrict__ ws, float* __restrict__ out) {
    extern __shared__ char smem[];
    char* Bs = smem;                 // [128][520] halves
    char* As[2] = { smem + B_BYTES, smem + B_BYTES + A_BYTES };  // [128][72] halves

    const uint32_t sbase = smem_u32_of(smem);
    const uint32_t aAddr[2] = { sbase + B_BYTES, sbase + B_BYTES + A_BYTES };

    const int tid  = threadIdx.x;
    const int lane = tid & 31;
    const int wid  = tid >> 5;
    const int wm   = wid & 3;        // warp M index (4)
    const int wn   = wid >> 2;       // warp N index (4)
    const long long blk = blockIdx.x;

    // ---- load B image into SMEM (restride 512 -> 520 halves) ----
    {
        const float4* src = reinterpret_cast<const float4*>(g_Bh);
#pragma unroll
        for (int p = 0; p < 16; p++) {
            int idx = tid + 512 * p;          // float4 units, 64 per row
            int row = idx >> 6, q = idx & 63;
            *reinterpret_cast<float4*>(Bs + row * (BSTRIDE_H * 2) + q * 16) = src[idx];
        }
    }

    const float4* wsv = reinterpret_cast<const float4*>(ws);

    float acc[2][4][4];
#pragma unroll
    for (int a = 0; a < 2; a++)
#pragma unroll
        for (int b = 0; b < 4; b++)
#pragma unroll
            for (int c = 0; c < 4; c++) acc[a][b][c] = 0.f;

    // ---- staging helpers ----
    float4 st[4];
    auto stage_ldg = [&](int chunk) {
#pragma unroll
        for (int p = 0; p < 4; p++) {
            int idx = tid + 512 * p;
            int row = idx >> 4, q = idx & 15;      // q: float4 within k64
            long long gr = blk * MT + row;
            if (gr >= NROWS) gr = NROWS - 1;
            st[p] = wsv[gr * (KD / 4) + chunk * (KC / 4) + q];
        }
    };
    auto stage_sts = [&](int buf) {
        char* ab = As[buf];
#pragma unroll
        for (int p = 0; p < 4; p++) {
            int idx = tid + 512 * p;
            int row = idx >> 4, q = idx & 15;
            __half2 h0 = __floats2half2_rn(st[p].x, st[p].y);
            __half2 h1 = __floats2half2_rn(st[p].z, st[p].w);
            uint2 v;
            v.x = *reinterpret_cast<uint32_t*>(&h0);
            v.y = *reinterpret_cast<uint32_t*>(&h1);
            *reinterpret_cast<uint2*>(ab + row * (ASTRIDE_H * 2) + q * 8) = v;
        }
    };

    auto mma_chunk = [&](int ch, int buf) {
        const uint32_t abase = aAddr[buf];
#pragma unroll
        for (int s = 0; s < 4; s++) {
            uint32_t afr[2][4];
#pragma unroll
            for (int tm = 0; tm < 2; tm++) {
                int row = wm * 32 + tm * 16 + (lane & 15);
                int hcol = s * 16 + (lane >> 4) * 8;
                ldsm4(afr[tm], abase + (uint32_t)(row * (ASTRIDE_H * 2) + hcol * 2));
            }
            uint32_t bfr[4][2];
#pragma unroll
            for (int tn = 0; tn < 4; tn++) {
                int n = wn * 32 + tn * 8 + (lane >> 2);
                int k = ch * KC + s * 16 + (lane & 3) * 2;
                const uint32_t* bp = reinterpret_cast<const uint32_t*>(
                    Bs + n * (BSTRIDE_H * 2) + k * 2);
                bfr[tn][0] = bp[0];
                bfr[tn][1] = bp[4];   // k+8 halves = +16B
            }
#pragma unroll
            for (int tm = 0; tm < 2; tm++)
#pragma unroll
                for (int tn = 0; tn < 4; tn++)
                    mma16816(acc[tm][tn], afr[tm], bfr[tn]);
        }
    };

    // ---- pipeline ----
    stage_ldg(0);
    stage_sts(0);
    __syncthreads();

#pragma unroll 1
    for (int ch = 0; ch < NKC; ch++) {
        if (ch + 1 < NKC) stage_ldg(ch + 1);
        mma_chunk(ch, ch & 1);
        if (ch + 1 < NKC) {
            stage_sts((ch + 1) & 1);
            __syncthreads();
        }
    }

    // ---- epilogue: direct register stores ----
#pragma unroll
    for (int tm = 0; tm < 2; tm++) {
        long long r0 = blk * MT + wm * 32 + tm * 16 + (lane >> 2);
        long long r1 = r0 + 8;
#pragma unroll
        for (int tn = 0; tn < 4; tn++) {
            int n0 = wn * 32 + tn * 8 + (lane & 3) * 2;
            int n1 = n0 + 1;
            const float* c = acc[tm][tn];
            if (r0 < NROWS) {
                if (n0 < NCHUNK) out[(size_t)n0 * NROWS + r0] = c[0];
                if (n1 < NCHUNK) out[(size_t)n1 * NROWS + r0] = c[1];
            }
            if (r1 < NROWS) {
                if (n0 < NCHUNK) out[(size_t)n0 * NROWS + r1] = c[2];
                if (n1 < NCHUNK) out[(size_t)n1 * NROWS + r1] = c[3];
            }
        }
    }
}

// ---------------------------- launcher -----------------------------------
extern "C" void kernel_launch(void* const* d_in, const int* in_sizes, int n_in,
                              void* d_out, int out_size) {
    const float* preference = (const float*)d_in[0];
    const float* pref_emb   = (const float*)d_in[1];
    const float* chunk_emb  = (const float*)d_in[2];
    const float* W1         = (const float*)d_in[3];
    const float* b1         = (const float*)d_in[4];
    const float* W2         = (const float*)d_in[5];
    const float* b2         = (const float*)d_in[6];
    const float* W3         = (const float*)d_in[7];
    const float* b3         = (const float*)d_in[8];
    const float* ws         = (const float*)d_in[9];
    float* out = (float*)d_out;

    float *px, *ph1, *ph2;
    cudaGetSymbolAddress((void**)&px,  g_x);
    cudaGetSymbolAddress((void**)&ph1, g_h1);
    cudaGetSymbolAddress((void**)&ph2, g_h2);

    cudaFuncSetAttribute(big_kernel, cudaFuncAttributeMaxDynamicSharedMemorySize,
                         SMEM_TOTAL);

    build_x_kernel<<<1, 256>>>(preference, pref_emb, chunk_emb);

    dim3 lgrid(HID / 32, (NCHUNK + 7) / 8);  // 16 x 14
    layer_kernel<IND1, true,  false><<<lgrid, 512>>>(px,  W1, b1, ph1);
    layer_kernel<HID,  true,  false><<<lgrid, 512>>>(ph1, W2, b2, ph2);
    layer_kernel<HID,  false, true ><<<lgrid, 512>>>(ph2, W3, b3, ph2 /*unused*/);

    int nblocks = (NROWS + MT - 1) / MT;     // 1719
    big_kernel<<<nblocks, 512, SMEM_TOTAL>>>(ws, out);
}

// round 5
// speedup vs baseline: 4.2574x; 1.0581x over previous
#include <cuda_runtime.h>
#include <cuda_fp16.h>
#include <cstdint>

#define NCHUNK 105
#define HID    512
#define IND1   128
#define NROWS  220000
#define KD     512

// ---- big GEMM tiling ----
#define MT    128          // M tile (ws rows)
#define NTP   128          // padded N
#define KC    32           // K chunk per stage
#define NKC   16           // 512/32
#define AST_H 40           // halves per A_s row (32 + 8 pad) -> 80B, conflict-free ldsm
#define BST_H 40           // halves per B_s row -> 80B, conflict-free lds.b32
#define ABUF_B (MT * AST_H * 2)    // 10240
#define BBUF_B (NTP * BST_H * 2)   // 10240

// ---------------- device scratch ----------------
__device__ float  g_x  [NCHUNK * IND1];
__device__ float  g_h1 [NCHUNK * HID];
__device__ float  g_h2 [NCHUNK * HID];
__device__ __half g_Bh [NTP * HID];        // fp16 image of rep (rows 105..127 zero)

// ---------------- PTX helpers ----------------
__device__ __forceinline__ uint32_t smem_u32_of(const void* p) {
    uint32_t a;
    asm("{ .reg .u64 t; cvta.to.shared.u64 t, %1; cvt.u32.u64 %0, t; }" : "=r"(a) : "l"(p));
    return a;
}
__device__ __forceinline__ void ldsm4(uint32_t* r, uint32_t addr) {
    asm volatile("ldmatrix.sync.aligned.m8n8.x4.shared.b16 {%0,%1,%2,%3}, [%4];"
                 : "=r"(r[0]), "=r"(r[1]), "=r"(r[2]), "=r"(r[3]) : "r"(addr));
}
__device__ __forceinline__ void mma16816(float* d, const uint32_t* a, const uint32_t* b) {
    asm volatile(
        "mma.sync.aligned.m16n8k16.row.col.f32.f16.f16.f32 "
        "{%0,%1,%2,%3}, {%4,%5,%6,%7}, {%8,%9}, {%0,%1,%2,%3};"
        : "+f"(d[0]), "+f"(d[1]), "+f"(d[2]), "+f"(d[3])
        : "r"(a[0]), "r"(a[1]), "r"(a[2]), "r"(a[3]), "r"(b[0]), "r"(b[1]));
}
__device__ __forceinline__ void cp16(uint32_t dst, const void* src) {
    asm volatile("cp.async.ca.shared.global [%0], [%1], 16;"
                 :: "r"(dst), "l"(src) : "memory");
}
__device__ __forceinline__ void cp_commit() {
    asm volatile("cp.async.commit_group;" ::: "memory");
}
__device__ __forceinline__ void cp_wait0() {
    asm volatile("cp.async.wait_group 0;" ::: "memory");
}

// ---------------- build x = [pref_embedding | chunk_emb] -----------------
__global__ __launch_bounds__(256)
void build_x_kernel(const float* __restrict__ preference,
                    const float* __restrict__ pref_emb,
                    const float* __restrict__ chunk_emb) {
    __shared__ float pe[64];
    int tid = threadIdx.x;
    if (tid < 64)
        pe[tid] = preference[0] * pref_emb[tid] + preference[1] * pref_emb[64 + tid];
    __syncthreads();
    for (int i = tid; i < NCHUNK * IND1; i += blockDim.x) {
        int c = i >> 7, k = i & 127;
        g_x[i] = (k < 64) ? pe[k] : chunk_emb[c * 64 + (k - 64)];
    }
    for (int i = tid; i < (NTP - NCHUNK) * HID; i += blockDim.x)
        g_Bh[NCHUNK * HID + i] = __float2half(0.f);
}

// ---------------- MLP layer (proven passing structure) -------------------
template <int IND, bool RELU, bool EMITB>
__global__ __launch_bounds__(512)
void layer_kernel(const float* __restrict__ in, const float* __restrict__ W,
                  const float* __restrict__ bias, float* __restrict__ out) {
    constexpr int JITER = 2;
    constexpr int Q = IND / 4;
    __shared__ float4 in_s[8][Q];

    int tid = threadIdx.x, lane = tid & 31, warp = tid >> 5;
    int cbase = blockIdx.y * 8;

    for (int i = tid; i < 8 * Q; i += 512) {
        int c = i / Q, q = i % Q;
        float4 v = make_float4(0.f, 0.f, 0.f, 0.f);
        if (cbase + c < NCHUNK)
            v = reinterpret_cast<const float4*>(in)[(cbase + c) * Q + q];
        in_s[c][q] = v;
    }
    __syncthreads();

    for (int t = 0; t < JITER; t++) {
        int j = blockIdx.x * (16 * JITER) + warp * JITER + t;
        float acc[8];
#pragma unroll
        for (int c = 0; c < 8; c++) acc[c] = 0.f;
        const float4* Wr = reinterpret_cast<const float4*>(W) + (size_t)j * Q;
        for (int i = lane; i < Q; i += 32) {
            float4 w = Wr[i];
#pragma unroll
            for (int c = 0; c < 8; c++) {
                float4 x = in_s[c][i];
                acc[c] += w.x * x.x + w.y * x.y + w.z * x.z + w.w * x.w;
            }
        }
#pragma unroll
        for (int c = 0; c < 8; c++) {
            float v = acc[c];
#pragma unroll
            for (int off = 16; off; off >>= 1) v += __shfl_down_sync(0xffffffffu, v, off);
            if (lane == 0 && (cbase + c) < NCHUNK) {
                v += bias[j];
                if (RELU) v = fmaxf(v, 0.f);
                if (EMITB)
                    g_Bh[(cbase + c) * HID + j] = __float2half_rn(v);
                else
                    out[(cbase + c) * HID + j] = v;
            }
        }
    }
}

// ---------------- big GEMM: out[n][m] = ws[m] . rep[n] (HMMA fp16) -------
// 256 threads, 8 warps (2 in M x 4 in N), warp tile 64m x 32n.
__global__ __launch_bounds__(256, 2)
void big_kernel(const float* __restrict__ ws, float* __restrict__ out) {
    __shared__ __align__(16) char As[2][ABUF_B];
    __shared__ __align__(16) char Bs[2][BBUF_B];

    const uint32_t aAddr[2] = { smem_u32_of(As[0]), smem_u32_of(As[1]) };
    const uint32_t bAddr[2] = { smem_u32_of(Bs[0]), smem_u32_of(Bs[1]) };

    const int tid   = threadIdx.x;
    const int lane  = tid & 31;
    const int wid   = tid >> 5;
    const int warpM = wid >> 2;      // 0..1
    const int warpN = wid & 3;       // 0..3
    const long long blk = blockIdx.x;

    const float4* wsv = reinterpret_cast<const float4*>(ws);
    const char*   bsrc = reinterpret_cast<const char*>(g_Bh);

    float acc[4][4][4];
#pragma unroll
    for (int a = 0; a < 4; a++)
#pragma unroll
        for (int b = 0; b < 4; b++)
#pragma unroll
            for (int c = 0; c < 4; c++) acc[a][b][c] = 0.f;

    // ---- staging helpers ----
    // A: 128 rows x 32 floats = 1024 float4; item = 8 consecutive floats.
    float4 pf[2][2];
    auto a_ldg = [&](int ch) {
#pragma unroll
        for (int p = 0; p < 2; p++) {
            int item = tid + 256 * p;           // 0..511
            int row = item >> 2, g = item & 3;
            long long gr = blk * MT + row;
            if (gr >= NROWS) gr = NROWS - 1;
            const float4* base = wsv + gr * (KD / 4) + ch * (KC / 4) + g * 2;
            pf[p][0] = base[0];
            pf[p][1] = base[1];
        }
    };
    auto a_sts = [&](int buf) {
#pragma unroll
        for (int p = 0; p < 2; p++) {
            int item = tid + 256 * p;
            int row = item >> 2, g = item & 3;
            __half2 h0 = __floats2half2_rn(pf[p][0].x, pf[p][0].y);
            __half2 h1 = __floats2half2_rn(pf[p][0].z, pf[p][0].w);
            __half2 h2 = __floats2half2_rn(pf[p][1].x, pf[p][1].y);
            __half2 h3 = __floats2half2_rn(pf[p][1].z, pf[p][1].w);
            uint4 v;
            v.x = *reinterpret_cast<uint32_t*>(&h0);
            v.y = *reinterpret_cast<uint32_t*>(&h1);
            v.z = *reinterpret_cast<uint32_t*>(&h2);
            v.w = *reinterpret_cast<uint32_t*>(&h3);
            *reinterpret_cast<uint4*>(&As[buf][row * (AST_H * 2) + g * 16]) = v;
        }
    };
    // B: 128 rows x 64B chunk slice = 512 x 16B cp.async
    auto b_cp = [&](int ch, int buf) {
#pragma unroll
        for (int p = 0; p < 2; p++) {
            int item = tid + 256 * p;           // 0..511
            int row = item >> 2, seg = item & 3;
            cp16(bAddr[buf] + (uint32_t)(row * (BST_H * 2) + seg * 16),
                 bsrc + row * (HID * 2) + ch * (KC * 2) + seg * 16);
        }
        cp_commit();
    };

    auto mma_chunk = [&](int buf) {
        const uint32_t ab = aAddr[buf];
        const uint32_t bb = bAddr[buf];
#pragma unroll
        for (int s = 0; s < 2; s++) {
            uint32_t afr[4][4];
#pragma unroll
            for (int tm = 0; tm < 4; tm++) {
                int row = warpM * 64 + tm * 16 + (lane & 15);
                int hcol = s * 16 + (lane >> 4) * 8;
                ldsm4(afr[tm], ab + (uint32_t)(row * (AST_H * 2) + hcol * 2));
            }
            uint32_t bfr[4][2];
#pragma unroll
            for (int tn = 0; tn < 4; tn++) {
                int n = warpN * 32 + tn * 8 + (lane >> 2);
                int kl = s * 16 + (lane & 3) * 2;
                const uint32_t* bp = reinterpret_cast<const uint32_t*>(
                    &Bs[buf][n * (BST_H * 2) + kl * 2]);
                bfr[tn][0] = bp[0];
                bfr[tn][1] = bp[4];   // +16B = +8 halves (k+8)
            }
#pragma unroll
            for (int tm = 0; tm < 4; tm++)
#pragma unroll
                for (int tn = 0; tn < 4; tn++)
                    mma16816(acc[tm][tn], afr[tm], bfr[tn]);
        }
    };

    // ---- pipeline (2-stage) ----
    b_cp(0, 0);
    a_ldg(0);
    a_sts(0);
    cp_wait0();
    __syncthreads();

#pragma unroll 1
    for (int ch = 0; ch < NKC; ch++) {
        int cur = ch & 1;
        if (ch + 1 < NKC) {
            b_cp(ch + 1, cur ^ 1);
            a_ldg(ch + 1);
        }
        mma_chunk(cur);
        if (ch + 1 < NKC) {
            a_sts(cur ^ 1);
            cp_wait0();
            __syncthreads();
        }
    }

    // ---- epilogue: direct register stores ----
#pragma unroll
    for (int tm = 0; tm < 4; tm++) {
        long long r0 = blk * MT + warpM * 64 + tm * 16 + (lane >> 2);
        long long r1 = r0 + 8;
#pragma unroll
        for (int tn = 0; tn < 4; tn++) {
            int n0 = warpN * 32 + tn * 8 + (lane & 3) * 2;
            int n1 = n0 + 1;
            const float* c = acc[tm][tn];
            if (r0 < NROWS) {
                if (n0 < NCHUNK) out[(size_t)n0 * NROWS + r0] = c[0];
                if (n1 < NCHUNK) out[(size_t)n1 * NROWS + r0] = c[1];
            }
            if (r1 < NROWS) {
                if (n0 < NCHUNK) out[(size_t)n0 * NROWS + r1] = c[2];
                if (n1 < NCHUNK) out[(size_t)n1 * NROWS + r1] = c[3];
            }
        }
    }
}

// ---------------------------- launcher -----------------------------------
extern "C" void kernel_launch(void* const* d_in, const int* in_sizes, int n_in,
                              void* d_out, int out_size) {
    const float* preference = (const float*)d_in[0];
    const float* pref_emb   = (const float*)d_in[1];
    const float* chunk_emb  = (const float*)d_in[2];
    const float* W1         = (const float*)d_in[3];
    const float* b1         = (const float*)d_in[4];
    const float* W2         = (const float*)d_in[5];
    const float* b2         = (const float*)d_in[6];
    const float* W3         = (const float*)d_in[7];
    const float* b3         = (const float*)d_in[8];
    const float* ws         = (const float*)d_in[9];
    float* out = (float*)d_out;

    float *px, *ph1, *ph2;
    cudaGetSymbolAddress((void**)&px,  g_x);
    cudaGetSymbolAddress((void**)&ph1, g_h1);
    cudaGetSymbolAddress((void**)&ph2, g_h2);

    build_x_kernel<<<1, 256>>>(preference, pref_emb, chunk_emb);

    dim3 lgrid(HID / 32, (NCHUNK + 7) / 8);  // 16 x 14
    layer_kernel<IND1, true,  false><<<lgrid, 512>>>(px,  W1, b1, ph1);
    layer_kernel<HID,  true,  false><<<lgrid, 512>>>(ph1, W2, b2, ph2);
    layer_kernel<HID,  false, true ><<<lgrid, 512>>>(ph2, W3, b3, ph2 /*unused*/);

    int nblocks = (NROWS + MT - 1) / MT;     // 1719
    big_kernel<<<nblocks, 256>>>(ws, out);
}